// round 13
// baseline (speedup 1.0000x reference)
#include <cuda_runtime.h>
#include <cstdint>

// Problem constants
#define ROWS   65536        // B*n = 8192*8
#define NE     1024         // codebook size
#define ED     64           // codebook dim
#define CHUNK  128          // codebook entries staged per iteration
#define NCHUNK (NE / CHUNK) // 8
#define RPB    64           // rows per block
#define TR     8            // rows per warp (8 warps * 8 = 64)
#define TE     4            // entries per lane per chunk (CHUNK/32)

// Output layout (tuple flattened, all float32) — validated R1-R12
#define OFF_LOSS  0
#define OFF_L1    1
#define OFF_L2    2
#define OFF_ZQST  3
#define OFF_ZOUT  4194307
#define OFF_PERP  8388611
#define OFF_OH    8388612
#define OFF_IDX   75497476

__device__ int    g_hist[NE];
__device__ double g_loss;
__device__ float  g_wsum[NE];

__device__ __forceinline__ void ffma2(unsigned long long &acc,
                                      unsigned long long a,
                                      unsigned long long b) {
    asm("fma.rn.f32x2 %0, %1, %2, %0;" : "+l"(acc) : "l"(a), "l"(b));
}
__device__ __forceinline__ float2 unpack2(unsigned long long v) {
    float2 r;
    asm("mov.b64 {%0, %1}, %2;" : "=f"(r.x), "=f"(r.y) : "l"(v));
    return r;
}

// ---------------------------------------------------------------------------
// prep: per-entry ||w||^2, zero histogram + loss accumulator
// ---------------------------------------------------------------------------
__global__ void vq_prep(const float* __restrict__ w) {
    int e = blockIdx.x, lane = threadIdx.x;
    const float* wr = w + e * ED;
    float a = wr[lane], b = wr[lane + 32];
    float s = a * a + b * b;
    #pragma unroll
    for (int o = 16; o; o >>= 1) s += __shfl_down_sync(0xffffffffu, s, o);
    if (lane == 0) {
        g_wsum[e] = s;
        g_hist[e] = 0;
        if (e == 0) g_loss = 0.0;
    }
}

// ---------------------------------------------------------------------------
// main kernel — R4 geometry (TR=8/TE=4/CHUNK=128, 1024 blocks) minus waste:
//  * NO xor swizzle: 8B accesses are 2-way-conflicted either way (bank-pair =
//    lane mod 16); dropping it turns per-dp address math into one IADD and
//    lets ptxas use LDS immediate offsets.
//  * staging: e-varies-with-lane assignment -> conflict-free STS.64, fully
//    coalesced 32B/lane LDG.128 pair reads.
//  * z via LDS.128 uniform broadcasts covering 2 dps.
// One-hot zeros fire-and-forget in the chunk loop; 1.0 after block fence.
// Scores bit-identical to R4: (||z||^2 + ||w||^2) - 2*dot, fp32, dp-ascending.
// ---------------------------------------------------------------------------
__global__ __launch_bounds__(256) void vq_argmin(
    const float* __restrict__ z, const float* __restrict__ w,
    float* __restrict__ out)
{
    __shared__ float  zs[RPB * ED];       // 16384 B: z tile (row-major)
    __shared__ float2 wp[32 * CHUNK];     // 32768 B: w chunk [dp][entry], NO swizzle

    const int tid = threadIdx.x, lane = tid & 31, warp = tid >> 5;
    const int rowBase = blockIdx.x * RPB;
    const int myRow0 = warp * TR;

    // stage z tile (coalesced float4)
    {
        const float4* zg = (const float4*)(z + (size_t)rowBase * ED);
        float4* zt = (float4*)zs;
        #pragma unroll
        for (int i = tid; i < RPB * ED / 4; i += 256) zt[i] = zg[i];
    }
    __syncthreads();

    // per-warp zsum: lane r (<8) owns row myRow0+r, sequential d-order (= R4)
    float myzsum = 0.f;
    if (lane < TR) {
        const float* zr = zs + (myRow0 + lane) * ED;
        #pragma unroll
        for (int d = 0; d < ED; d++) myzsum += zr[d] * zr[d];
    }

    float best[TR]; int bidx[TR];
    #pragma unroll
    for (int r = 0; r < TR; r++) { best[r] = 3.402823e38f; bidx[r] = 0x7fffffff; }

    const unsigned long long* zs2 = (const unsigned long long*)zs;  // 32 ull/row
    float4* ohp = (float4*)(out + OFF_OH + (size_t)rowBase * NE);
    const float4 zero4 = make_float4(0.f, 0.f, 0.f, 0.f);

    for (int c = 0; c < NE; c += CHUNK) {
        __syncthreads();   // protect wp reuse
        // stage w chunk into [dp][entry] (no swizzle).
        // slot i (< CHUNK*8): e = i & 127 (lane-contiguous), seg = i >> 7.
        // Read 32B (2x LDG.128) of entry e's dims [8seg..8seg+7] -> 4 STS.64
        // to rows dp=4seg..4seg+3. Stores: bank-pair = e mod 16 -> 2-way max.
        {
            const float4* wg4 = (const float4*)(w + (size_t)c * ED);
            #pragma unroll
            for (int k = 0; k < 2; k++) {
                int i = k * 256 + tid;            // 0..511
                int e = i & (CHUNK - 1);
                int seg = i >> 7;                 // 0..3
                float4 q0 = wg4[e * 16 + seg * 4];
                float4 q1 = wg4[e * 16 + seg * 4 + 1];
                float4 q2 = wg4[e * 16 + seg * 4 + 2];
                float4 q3 = wg4[e * 16 + seg * 4 + 3];
                int dp0 = seg * 8;
                wp[(dp0 + 0) * CHUNK + e] = make_float2(q0.x, q0.y);
                wp[(dp0 + 1) * CHUNK + e] = make_float2(q0.z, q0.w);
                wp[(dp0 + 2) * CHUNK + e] = make_float2(q1.x, q1.y);
                wp[(dp0 + 3) * CHUNK + e] = make_float2(q1.z, q1.w);
                wp[(dp0 + 4) * CHUNK + e] = make_float2(q2.x, q2.y);
                wp[(dp0 + 5) * CHUNK + e] = make_float2(q2.z, q2.w);
                wp[(dp0 + 6) * CHUNK + e] = make_float2(q3.x, q3.y);
                wp[(dp0 + 7) * CHUNK + e] = make_float2(q3.z, q3.w);
            }
        }
        __syncthreads();

        // fire-and-forget: zero 1/NCHUNK of this block's one-hot slice
        {
            int it = c / CHUNK;                    // 0..7
            #pragma unroll
            for (int k = 0; k < (RPB * NE / 4) / (NCHUNK * 256); k++)
                ohp[it * (RPB * NE / 4 / NCHUNK) + k * 256 + tid] = zero4;
        }

        unsigned long long acc[TR][TE];
        #pragma unroll
        for (int r = 0; r < TR; r++)
            #pragma unroll
            for (int j = 0; j < TE; j++) acc[r][j] = 0ull;

        #pragma unroll 4
        for (int dp2 = 0; dp2 < 16; dp2++) {
            // z: one LDS.128 uniform broadcast covers dps (2*dp2, 2*dp2+1)
            ulonglong2 zv2[TR];
            #pragma unroll
            for (int r = 0; r < TR; r++)
                zv2[r] = *(const ulonglong2*)&zs2[(myRow0 + r) * 32 + 2 * dp2];
            #pragma unroll
            for (int h = 0; h < 2; h++) {
                const int dp = 2 * dp2 + h;
                unsigned long long wv[TE];
                #pragma unroll
                for (int j = 0; j < TE; j++)       // addr = base + dp*1024 + j*256 + lane*8
                    wv[j] = *(const unsigned long long*)&wp[dp * CHUNK + (j << 5) + lane];
                #pragma unroll
                for (int r = 0; r < TR; r++) {
                    unsigned long long zv = h ? zv2[r].y : zv2[r].x;
                    #pragma unroll
                    for (int j = 0; j < TE; j++)
                        ffma2(acc[r][j], zv, wv[j]);
                }
            }
        }

        #pragma unroll
        for (int r = 0; r < TR; r++) {
            float zsr = __shfl_sync(0xffffffffu, myzsum, r);
            #pragma unroll
            for (int j = 0; j < TE; j++) {
                float2 a = unpack2(acc[r][j]);
                float dot = a.x + a.y;
                int e = c + (j << 5) + lane;
                float t = zsr + g_wsum[e];
                float s = t - 2.0f * dot;      // matches reference fp32 ordering
                if (s < best[r] || (s == best[r] && e < bidx[r])) {
                    best[r] = s; bidx[r] = e;
                }
            }
        }
    }

    __syncthreads();   // fence: all one-hot zeros precede the 1.0 stores below

    // per-row warp reduction + epilogue
    double dacc = 0.0;
    #pragma unroll
    for (int r = 0; r < TR; r++) {
        float v = best[r]; int id = bidx[r];
        #pragma unroll
        for (int o = 16; o; o >>= 1) {
            float v2 = __shfl_down_sync(0xffffffffu, v, o);
            int   i2 = __shfl_down_sync(0xffffffffu, id, o);
            if (v2 < v || (v2 == v && i2 < id)) { v = v2; id = i2; }
        }
        id = __shfl_sync(0xffffffffu, id, 0);

        int grow = rowBase + myRow0 + r;
        const float* wrow = w + (size_t)id * ED;
        float dsq = 0.f;
        #pragma unroll
        for (int d = lane; d < ED; d += 32) {
            float zq = wrow[d];                  // z_q = exact codebook row
            float zr = zs[(myRow0 + r) * ED + d];
            float df = zq - zr;
            float st = zr + df;                  // straight-through fp32 replay
            out[OFF_ZQST + (size_t)grow * ED + d] = st;
            out[OFF_ZOUT + (size_t)grow * ED + d] = st;
            dsq += df * df;
        }
        #pragma unroll
        for (int o = 16; o; o >>= 1) dsq += __shfl_down_sync(0xffffffffu, dsq, o);
        if (lane == 0) {
            atomicAdd(&g_hist[id], 1);
            out[OFF_IDX + grow] = (float)id;
            out[OFF_OH + (size_t)grow * NE + id] = 1.0f;   // after fenced zeros
            dacc += (double)dsq;
        }
    }
    if (lane == 0 && dacc != 0.0) atomicAdd(&g_loss, dacc);
}

// ---------------------------------------------------------------------------
// finalize: losses + perplexity scalars
// ---------------------------------------------------------------------------
__global__ void vq_finalize(float* __restrict__ out) {
    __shared__ float red[1024];
    int t = threadIdx.x;
    float p = (float)g_hist[t] / 65536.0f;
    red[t] = p * logf(p + 1e-10f);
    __syncthreads();
    #pragma unroll
    for (int s = 512; s; s >>= 1) {
        if (t < s) red[t] += red[t + s];
        __syncthreads();
    }
    if (t == 0) {
        out[OFF_PERP] = expf(-red[0]);
        float l1 = (float)(g_loss / 4194304.0);
        out[OFF_L1] = l1;
        out[OFF_L2] = l1;                 // loss2 == loss1 numerically
        out[OFF_LOSS] = l1 + 0.25f * l1;  // GAMMA*l1 + BETA*l2
    }
}

// ---------------------------------------------------------------------------
extern "C" void kernel_launch(void* const* d_in, const int* in_sizes, int n_in,
                              void* d_out, int out_size)
{
    const float* z = (const float*)d_in[0];   // (8192, 512)
    const float* w = (const float*)d_in[1];   // (1024, 64)
    float* out = (float*)d_out;

    vq_prep<<<NE, 32>>>(w);
    vq_argmin<<<ROWS / RPB, 256>>>(z, w, out);
    vq_finalize<<<1, 1024>>>(out);
}